// round 17
// baseline (speedup 1.0000x reference)
#include <cuda_runtime.h>
#include <cuda_fp16.h>
#include <cstdint>

// ---------------- problem constants ----------------
#define NB      2048
#define NTOK    49
#define DIMC    512
#define QKV_N   1536
#define NHEAD   16
#define HDIM    32
#define NWIN    64
#define M_TOTAL (NB * NTOK)   // 100352

// ---------------- scratch (no allocs allowed) ----------------
__device__ __half g_qvh[(size_t)M_TOTAL * QKV_N];   // qkv fp16
__device__ __half g_xhi[(size_t)M_TOTAL * DIMC];
__device__ __half g_ahi[(size_t)M_TOTAL * DIMC];
__device__ __half g_wq_h[(size_t)QKV_N * DIMC];
__device__ __half g_wp_h[(size_t)DIMC * DIMC];
__device__ __half g_comb[(size_t)NWIN * NHEAD * 64 * 64];  // bias+mask fp16, pad -60000

// ---------------- helpers ----------------
__device__ __forceinline__ uint32_t smem_to_u32(const void* p) {
    uint32_t a;
    asm("{ .reg .u64 t; cvta.to.shared.u64 t, %1; cvt.u32.u64 %0, t; }" : "=r"(a) : "l"(p));
    return a;
}
__device__ __forceinline__ void cp_async16(uint32_t saddr, const void* gaddr) {
    asm volatile("cp.async.cg.shared.global [%0], [%1], 16;" :: "r"(saddr), "l"(gaddr));
}
#define CP_COMMIT() asm volatile("cp.async.commit_group;")
#define CP_WAIT0()  asm volatile("cp.async.wait_group 0;")
#define CP_WAIT1()  asm volatile("cp.async.wait_group 1;")

__device__ __forceinline__ void ldsm4(uint32_t* r, uint32_t addr) {
    asm volatile("ldmatrix.sync.aligned.m8n8.x4.shared.b16 {%0,%1,%2,%3}, [%4];"
                 : "=r"(r[0]), "=r"(r[1]), "=r"(r[2]), "=r"(r[3]) : "r"(addr));
}
__device__ __forceinline__ void ldsm4t(uint32_t* r, uint32_t addr) {
    asm volatile("ldmatrix.sync.aligned.m8n8.x4.trans.shared.b16 {%0,%1,%2,%3}, [%4];"
                 : "=r"(r[0]), "=r"(r[1]), "=r"(r[2]), "=r"(r[3]) : "r"(addr));
}
__device__ __forceinline__ void mma16816(float* d, const uint32_t* a,
                                         uint32_t b0, uint32_t b1) {
    asm volatile(
        "mma.sync.aligned.m16n8k16.row.col.f32.f16.f16.f32 "
        "{%0,%1,%2,%3}, {%4,%5,%6,%7}, {%8,%9}, {%0,%1,%2,%3};"
        : "+f"(d[0]), "+f"(d[1]), "+f"(d[2]), "+f"(d[3])
        : "r"(a[0]), "r"(a[1]), "r"(a[2]), "r"(a[3]), "r"(b0), "r"(b1));
}
__device__ __forceinline__ uint32_t pack2(__half a, __half b) {
    __half2 t = __halves2half2(a, b);
    return *reinterpret_cast<uint32_t*>(&t);
}

// ---------------- conversion kernels ----------------
__global__ void __launch_bounds__(256) convert_h_kernel(
    const float* __restrict__ src, __half* __restrict__ hi, size_t n4)
{
    size_t i = (size_t)blockIdx.x * 256 + threadIdx.x;
    if (i >= n4) return;
    float4 v = reinterpret_cast<const float4*>(src)[i];
    uint2 uh{pack2(__float2half_rn(v.x), __float2half_rn(v.y)),
             pack2(__float2half_rn(v.z), __float2half_rn(v.w))};
    reinterpret_cast<uint2*>(hi)[i] = uh;
}

// tiled transpose: W [K][N] fp32 -> W^T [N][K] fp16, coalesced both sides
__global__ void __launch_bounds__(256) wh_t_kernel(
    const float* __restrict__ w, __half* __restrict__ hi, int K, int N)
{
    __shared__ float tile[32][33];
    const int k0 = blockIdx.y * 32;
    const int n0 = blockIdx.x * 32;
    const int tx = threadIdx.x & 31;
    const int ty = threadIdx.x >> 5;   // 0..7
    #pragma unroll
    for (int i = 0; i < 4; i++) {
        int k = ty + i * 8;
        tile[k][tx] = w[(size_t)(k0 + k) * N + n0 + tx];
    }
    __syncthreads();
    #pragma unroll
    for (int i = 0; i < 4; i++) {
        int n = ty + i * 8;
        hi[(size_t)(n0 + n) * K + k0 + tx] = __float2half_rn(tile[tx][n]);
    }
}

// combined[w][h][64][64] = fp16(bias + mask), padded with -60000
__global__ void __launch_bounds__(256) combined_kernel(
    const float* __restrict__ bias_table, const int* __restrict__ rel_idx,
    const float* __restrict__ mask, __half* __restrict__ comb)
{
    const int w = blockIdx.x, h = blockIdx.y;
    __half* dst = comb + ((size_t)(w * NHEAD + h)) * 4096;
    for (int i = threadIdx.x; i < 4096; i += 256) {
        int n = i >> 6, m = i & 63;
        float v = -60000.f;
        if (n < NTOK && m < NTOK)
            v = bias_table[rel_idx[n * NTOK + m] * NHEAD + h]
              + mask[((size_t)w * NTOK + n) * NTOK + m];
        dst[i] = __float2half_rn(v);
    }
}

// ---------------- mma.sync plain fp16 GEMM: C = A @ B^T + bias -------------
// 128x128x64 tiles, 8 warps, 3-stage cp.async pipeline, 2 CTAs/SM.
#define STAGE_BYTES 32768
#define NSTAGE      3
#define GEMM_SMEM   (NSTAGE * STAGE_BYTES)

__device__ __forceinline__ uint32_t sw_addr(uint32_t base, int row, int chunk) {
    return base + row * 128 + ((chunk ^ (row & 7)) << 4);
}

template<bool HOUT>
__global__ void __launch_bounds__(256, 2) gemm1_kernel(
    const __half* __restrict__ Ah, const __half* __restrict__ Bh,
    const float* __restrict__ bias, float* __restrict__ C,
    __half* __restrict__ Chi,
    int M, int N, int K)
{
    extern __shared__ char smem[];
    const uint32_t sbase = smem_to_u32(smem);
    const int tid  = threadIdx.x;
    const int lane = tid & 31;
    const int wid  = tid >> 5;
    const int warp_m = wid & 3;
    const int warp_n = wid >> 2;
    const int m0 = blockIdx.y * 128;
    const int n0 = blockIdx.x * 128;
    const int NKT = K >> 6;

    float acc[2][8][4];
    #pragma unroll
    for (int i = 0; i < 2; i++)
        #pragma unroll
        for (int j = 0; j < 8; j++)
            #pragma unroll
            for (int t = 0; t < 4; t++) acc[i][j][t] = 0.f;

    auto load_stage = [&](int kt, int s) {
        const uint32_t sb = sbase + s * STAGE_BYTES;
        const int kofs = kt * 64;
        #pragma unroll
        for (int i = 0; i < 4; i++) {
            int f   = tid + i * 256;
            int row = f >> 3;
            int c   = f & 7;
            uint32_t sw = sw_addr(0, row, c);
            size_t ga = (size_t)(m0 + row) * K + kofs + c * 8;
            size_t gb = (size_t)(n0 + row) * K + kofs + c * 8;
            cp_async16(sb + sw,         Ah + ga);
            cp_async16(sb + 16384 + sw, Bh + gb);
        }
        CP_COMMIT();
    };

    load_stage(0, 0);
    if (NKT > 1) load_stage(1, 1);

    for (int kt = 0; kt < NKT; kt++) {
        const int s = kt % NSTAGE;
        if (kt + 1 < NKT) CP_WAIT1(); else CP_WAIT0();
        __syncthreads();
        if (kt + 2 < NKT) load_stage(kt + 2, (kt + 2) % NSTAGE);

        const uint32_t sA = sbase + s * STAGE_BYTES;
        const uint32_t sB = sA + 16384;

        #pragma unroll
        for (int ks = 0; ks < 4; ks++) {
            uint32_t ah[2][4];
            {
                const int arow = warp_m * 32 + (lane & 15);
                const int achk = 2 * ks + (lane >> 4);
                #pragma unroll
                for (int mt = 0; mt < 2; mt++)
                    ldsm4(ah[mt], sw_addr(sA, arow + mt * 16, achk));
            }
            uint32_t bh[4][4];
            {
                const int brow_base = warp_n * 64 + ((lane & 16) ? 8 : 0) + (lane & 7);
                const int bchk = 2 * ks + ((lane >> 3) & 1);
                #pragma unroll
                for (int p = 0; p < 4; p++)
                    ldsm4(bh[p], sw_addr(sB, brow_base + p * 16, bchk));
            }
            #pragma unroll
            for (int mt = 0; mt < 2; mt++)
                #pragma unroll
                for (int p = 0; p < 4; p++)
                    #pragma unroll
                    for (int hlf = 0; hlf < 2; hlf++)
                        mma16816(acc[mt][p * 2 + hlf], ah[mt],
                                 bh[p][hlf*2], bh[p][hlf*2+1]);
        }
        __syncthreads();
    }

    const int row0 = m0 + warp_m * 32 + (lane >> 2);
    const int col0 = n0 + warp_n * 64 + (lane & 3) * 2;
    #pragma unroll
    for (int mt = 0; mt < 2; mt++)
        #pragma unroll
        for (int nt = 0; nt < 8; nt++) {
            const int c = col0 + nt * 8;
            const float b0 = bias[c], b1 = bias[c + 1];
            const int r0 = row0 + mt * 16;
            float v00 = acc[mt][nt][0] + b0, v01 = acc[mt][nt][1] + b1;
            float v10 = acc[mt][nt][2] + b0, v11 = acc[mt][nt][3] + b1;
            if (HOUT) {
                *reinterpret_cast<uint32_t*>(Chi + (size_t)r0 * N + c) =
                    pack2(__float2half_rn(v00), __float2half_rn(v01));
                *reinterpret_cast<uint32_t*>(Chi + (size_t)(r0 + 8) * N + c) =
                    pack2(__float2half_rn(v10), __float2half_rn(v11));
            } else {
                *reinterpret_cast<float2*>(C + (size_t)r0 * N + c)       = float2{v00, v01};
                *reinterpret_cast<float2*>(C + (size_t)(r0 + 8) * N + c) = float2{v10, v11};
            }
        }
}

// ---------------- batched tensor-core window attention ---------------------
#define AQ_STRIDE 40
#define A_TENSOR  2560
#define A_STAGE   7680
#define A_COMB    4096
#define A_SM_HALVES (A_COMB + 2 * A_STAGE)
#define NZ        4
#define NITER_PER (NB / NWIN / NZ)       // 8

__global__ void __launch_bounds__(128) attn_mma_kernel(
    const __half* __restrict__ qvh, const __half* __restrict__ comb,
    __half* __restrict__ out_hi)
{
    const int w = blockIdx.x;
    const int h = blockIdx.y;
    const int z = blockIdx.z;
    const int tid  = threadIdx.x;
    const int lane = tid & 31;
    const int wid  = tid >> 5;

    __shared__ __align__(16) __half sm[A_SM_HALVES];

    {
        const __half* cbg = comb + ((size_t)(w * NHEAD + h)) * 4096;
        for (int i = tid; i < A_COMB / 8; i += 128)
            reinterpret_cast<uint4*>(sm)[i] =
                reinterpret_cast<const uint4*>(cbg)[i];
        for (int i = tid; i < 2 * 3 * 15 * 5; i += 128) {
            int q8  = i % 5;
            int row = (i / 5) % 15;
            int t   = (i / 75) % 3;
            int s   = i / 225;
            uint32_t off = A_COMB + s * A_STAGE + t * A_TENSOR
                         + (49 + row) * AQ_STRIDE + q8 * 8;
            *reinterpret_cast<uint4*>(sm + off) = uint4{0, 0, 0, 0};
        }
    }
    __syncthreads();

    auto load_win = [&](int it, int s) {
        const int b = 64 * (z * NITER_PER + it) + w;
        const uint32_t sb = smem_to_u32(sm + A_COMB + s * A_STAGE);
        for (int i = tid; i < NTOK * 4; i += 128) {
            int n = i >> 2;
            int c = i & 3;
            const __half* src = qvh + (size_t)(b * NTOK + n) * QKV_N
                              + h * HDIM + c * 8;
            uint32_t dst = sb + (n * AQ_STRIDE + c * 8) * 2;
            cp_async16(dst,                    src);
            cp_async16(dst + A_TENSOR * 2,     src + DIMC);
            cp_async16(dst + 2 * A_TENSOR * 2, src + 2 * DIMC);
        }
        CP_COMMIT();
    };

    load_win(0, 0);

    const float scale = 0.17677669529663687f;
    const int r0 = wid * 16 + (lane >> 2);
    const int r1 = r0 + 8;
    const int cbase = 2 * (lane & 3);

    for (int it = 0; it < NITER_PER; it++) {
        const int s = it & 1;
        if (it + 1 < NITER_PER) { load_win(it + 1, s ^ 1); CP_WAIT1(); }
        else                    { CP_WAIT0(); }
        __syncthreads();

        const uint32_t uQH = smem_to_u32(sm + A_COMB + s * A_STAGE);
        const uint32_t uKH = uQH + A_TENSOR * 2;
        const uint32_t uVH = uQH + 2 * A_TENSOR * 2;
        const int b = 64 * (z * NITER_PER + it) + w;

        float acc[8][4];
        #pragma unroll
        for (int nt = 0; nt < 8; nt++)
            #pragma unroll
            for (int t = 0; t < 4; t++) acc[nt][t] = 0.f;

        #pragma unroll
        for (int ks = 0; ks < 2; ks++) {
            uint32_t aqh[4];
            const int arow = wid * 16 + (lane & 15);
            const int achk = 2 * ks + (lane >> 4);
            ldsm4(aqh, uQH + (arow * AQ_STRIDE + achk * 8) * 2);
            #pragma unroll
            for (int p = 0; p < 4; p++) {
                uint32_t bkh[4];
                const int brow = p * 16 + ((lane & 16) ? 8 : 0) + (lane & 7);
                const int bchk = 2 * ks + ((lane >> 3) & 1);
                ldsm4(bkh, uKH + (brow * AQ_STRIDE + bchk * 8) * 2);
                #pragma unroll
                for (int hlf = 0; hlf < 2; hlf++)
                    mma16816(acc[p * 2 + hlf], aqh, bkh[hlf*2], bkh[hlf*2+1]);
            }
        }

        #pragma unroll
        for (int nt = 0; nt < 8; nt++) {
            uint32_t u0 = *reinterpret_cast<const uint32_t*>(sm + r0 * 64 + nt * 8 + cbase);
            uint32_t u1 = *reinterpret_cast<const uint32_t*>(sm + r1 * 64 + nt * 8 + cbase);
            float2 c0 = __half22float2(*reinterpret_cast<__half2*>(&u0));
            float2 c1 = __half22float2(*reinterpret_cast<__half2*>(&u1));
            acc[nt][0] = acc[nt][0] * scale + c0.x;
            acc[nt][1] = acc[nt][1] * scale + c0.y;
            acc[nt][2] = acc[nt][2] * scale + c1.x;
            acc[nt][3] = acc[nt][3] * scale + c1.y;
        }
        float mx0 = -1e30f, mx1 = -1e30f;
        #pragma unroll
        for (int nt = 0; nt < 8; nt++) {
            mx0 = fmaxf(mx0, fmaxf(acc[nt][0], acc[nt][1]));
            mx1 = fmaxf(mx1, fmaxf(acc[nt][2], acc[nt][3]));
        }
        mx0 = fmaxf(mx0, __shfl_xor_sync(0xffffffff, mx0, 1));
        mx0 = fmaxf(mx0, __shfl_xor_sync(0xffffffff, mx0, 2));
        mx1 = fmaxf(mx1, __shfl_xor_sync(0xffffffff, mx1, 1));
        mx1 = fmaxf(mx1, __shfl_xor_sync(0xffffffff, mx1, 2));
        float sum0 = 0.f, sum1 = 0.f;
        #pragma unroll
        for (int nt = 0; nt < 8; nt++) {
            acc[nt][0] = __expf(acc[nt][0] - mx0);
            acc[nt][1] = __expf(acc[nt][1] - mx0);
            acc[nt][2] = __expf(acc[nt][2] - mx1);
            acc[nt][3] = __expf(acc[nt][3] - mx1);
            sum0 += acc[nt][0] + acc[nt][1];
            sum1 += acc[nt][2] + acc[nt][3];
        }
        sum0 += __shfl_xor_sync(0xffffffff, sum0, 1);
        sum0 += __shfl_xor_sync(0xffffffff, sum0, 2);
        sum1 += __shfl_xor_sync(0xffffffff, sum1, 1);
        sum1 += __shfl_xor_sync(0xffffffff, sum1, 2);
        const float sinv0 = 1.f / sum0;
        const float sinv1 = 1.f / sum1;

        uint32_t aph[4][4];
        #pragma unroll
        for (int kk = 0; kk < 4; kk++) {
            const int n0t = 2 * kk, n1t = 2 * kk + 1;
            aph[kk][0] = pack2(__float2half_rn(acc[n0t][0]), __float2half_rn(acc[n0t][1]));
            aph[kk][1] = pack2(__float2half_rn(acc[n0t][2]), __float2half_rn(acc[n0t][3]));
            aph[kk][2] = pack2(__float2half_rn(acc[n1t][0]), __float2half_rn(acc[n1t][1]));
            aph[kk][3] = pack2(__float2half_rn(acc[n1t][2]), __float2half_rn(acc[n1t][3]));
        }

        float oacc[4][4];
        #pragma unroll
        for (int nt = 0; nt < 4; nt++)
            #pragma unroll
            for (int t = 0; t < 4; t++) oacc[nt][t] = 0.f;

        #pragma unroll
        for (int ks = 0; ks < 4; ks++) {
            const int krow = ks * 16 + ((lane & 8) ? 8 : 0) + (lane & 7);
            #pragma unroll
            for (int p = 0; p < 2; p++) {
                uint32_t bvh[4];
                const int ncol = p * 16 + ((lane & 16) ? 8 : 0);
                ldsm4t(bvh, uVH + (krow * AQ_STRIDE + ncol) * 2);
                #pragma unroll
                for (int hlf = 0; hlf < 2; hlf++)
                    mma16816(oacc[p * 2 + hlf], aph[ks], bvh[hlf*2], bvh[hlf*2+1]);
            }
        }

        #pragma unroll
        for (int nt = 0; nt < 4; nt++) {
            const int d = nt * 8 + cbase;
            if (r0 < NTOK) {
                size_t base = (size_t)(b * NTOK + r0) * DIMC + h * HDIM + d;
                *reinterpret_cast<uint32_t*>(out_hi + base) =
                    pack2(__float2half_rn(oacc[nt][0] * sinv0),
                          __float2half_rn(oacc[nt][1] * sinv0));
            }
            if (r1 < NTOK) {
                size_t base = (size_t)(b * NTOK + r1) * DIMC + h * HDIM + d;
                *reinterpret_cast<uint32_t*>(out_hi + base) =
                    pack2(__float2half_rn(oacc[nt][2] * sinv1),
                          __float2half_rn(oacc[nt][3] * sinv1));
            }
        }
        __syncthreads();
    }
}

// ---------------- launcher ----------------
extern "C" void kernel_launch(void* const* d_in, const int* in_sizes, int n_in,
                              void* d_out, int out_size)
{
    const float* x          = (const float*)d_in[0];
    const float* mask       = (const float*)d_in[1];
    const float* qkv_w      = (const float*)d_in[2];
    const float* qkv_b      = (const float*)d_in[3];
    const float* proj_w     = (const float*)d_in[4];
    const float* proj_b     = (const float*)d_in[5];
    const float* bias_table = (const float*)d_in[6];
    const int*   rel_idx    = (const int*)d_in[7];
    float* out = (float*)d_out;

    __half *qvh, *xhi, *ahi, *wqh, *wph, *comb;
    cudaGetSymbolAddress((void**)&qvh, g_qvh);
    cudaGetSymbolAddress((void**)&xhi, g_xhi);
    cudaGetSymbolAddress((void**)&ahi, g_ahi);
    cudaGetSymbolAddress((void**)&wqh, g_wq_h);
    cudaGetSymbolAddress((void**)&wph, g_wp_h);
    cudaGetSymbolAddress((void**)&comb, g_comb);

    cudaFuncSetAttribute(gemm1_kernel<true>,  cudaFuncAttributeMaxDynamicSharedMemorySize, GEMM_SMEM);
    cudaFuncSetAttribute(gemm1_kernel<false>, cudaFuncAttributeMaxDynamicSharedMemorySize, GEMM_SMEM);

    size_t n4 = (size_t)M_TOTAL * DIMC / 4;
    convert_h_kernel<<<(unsigned)((n4 + 255) / 256), 256>>>(x, xhi, n4);
    wh_t_kernel<<<dim3(QKV_N / 32, DIMC / 32), 256>>>(qkv_w, wqh, DIMC, QKV_N);
    wh_t_kernel<<<dim3(DIMC / 32, DIMC / 32), 256>>>(proj_w, wph, DIMC, DIMC);
    combined_kernel<<<dim3(NWIN, NHEAD), 256>>>(bias_table, rel_idx, mask, comb);

    // 1) QKV projection -> fp16
    dim3 g1(QKV_N / 128, M_TOTAL / 128);
    gemm1_kernel<true><<<g1, 256, GEMM_SMEM>>>(xhi, wqh, qkv_b,
                                               nullptr, qvh,
                                               M_TOTAL, QKV_N, DIMC);

    // 2) batched tensor-core window attention -> fp16
    dim3 g2(NWIN, NHEAD, NZ);
    attn_mma_kernel<<<g2, 128>>>(qvh, comb, ahi);

    // 3) output projection -> fp32
    dim3 g3(DIMC / 128, M_TOTAL / 128);
    gemm1_kernel<false><<<g3, 256, GEMM_SMEM>>>(ahi, wph, proj_b,
                                                out, nullptr,
                                                M_TOTAL, DIMC, DIMC);
}